// round 10
// baseline (speedup 1.0000x reference)
#include <cuda_runtime.h>
#include <cuda_fp16.h>
#include <cstdint>

// ============================================================================
// Problem constants
// ============================================================================
#define N_ROWS   65536
#define IN_DIM   256
#define OUT_DIM  256
#define NTYPES   8
#define BM       128                       // rows per block tile
#define BN       128                       // cols per block tile (OUT split in 2)
#define MAXTILES (N_ROWS / BM + NTYPES)    // 520 row-tiles
#define KC       64                        // K-chunk (floats)
#define NCHUNK   (IN_DIM / KC)             // 4
#define GTHREADS 256
#define HIST_BLOCKS 64
#define WCONV_BLOCKS 512

// SMEM layout (bytes):
//  [0]      s_idx[128]     512B
//  [512]    s_bias[128]    512B
//  [1024]   2 stages x (A fp32 128x272B = 34816 | B fp16 16384) = 102400
#define OFF_STAGE0  1024
#define A_PITCH     272
#define A_BYTES     (128 * A_PITCH)        // 34816
#define STAGE_BYTES (A_BYTES + 16384)      // 51200
#define SMEM_BYTES  (OFF_STAGE0 + 2 * STAGE_BYTES)   // 103424

// ============================================================================
// Device scratch
// ============================================================================
__device__ int g_counts[NTYPES];   // self-resetting across graph replays
__device__ int g_cursor[NTYPES];   // self-resetting across graph replays
__device__ int g_padstart[NTYPES];
__device__ int g_idx[MAXTILES * BM];
__device__ int g_tiletype[MAXTILES];
__device__ __align__(16) __half g_Wh[NTYPES * OUT_DIM * IN_DIM];

// ============================================================================
// Helpers
// ============================================================================
__device__ __forceinline__ uint32_t smem_u32(const void* p) {
    uint32_t a;
    asm("{ .reg .u64 t; cvta.to.shared.u64 t, %1; cvt.u32.u64 %0, t; }" : "=r"(a) : "l"(p));
    return a;
}

__device__ __forceinline__ uint32_t swz(uint32_t off) { return off ^ ((off >> 3) & 0x70); }

__device__ __forceinline__ void cpa16(uint32_t dst, const void* src) {
    asm volatile("cp.async.cg.shared.global [%0], [%1], 16;" :: "r"(dst), "l"(src));
}
__device__ __forceinline__ void cpa_commit() {
    asm volatile("cp.async.commit_group;");
}
template <int N> __device__ __forceinline__ void cpa_wait() {
    asm volatile("cp.async.wait_group %0;" :: "n"(N) : "memory");
}

__device__ __forceinline__ void ldsm4(uint32_t* r, uint32_t addr) {
    asm volatile("ldmatrix.sync.aligned.m8n8.x4.shared.b16 {%0,%1,%2,%3}, [%4];"
                 : "=r"(r[0]), "=r"(r[1]), "=r"(r[2]), "=r"(r[3]) : "r"(addr));
}

__device__ __forceinline__ void mma16816(float* c, const uint32_t* a, uint32_t b0, uint32_t b1) {
    asm volatile("mma.sync.aligned.m16n8k16.row.col.f32.f16.f16.f32 "
                 "{%0,%1,%2,%3}, {%4,%5,%6,%7}, {%8,%9}, {%0,%1,%2,%3};"
                 : "+f"(c[0]), "+f"(c[1]), "+f"(c[2]), "+f"(c[3])
                 : "r"(a[0]), "r"(a[1]), "r"(a[2]), "r"(a[3]), "r"(b0), "r"(b1));
}

__device__ __forceinline__ uint32_t h2_as_u32(__half2 h) {
    return *reinterpret_cast<uint32_t*>(&h);
}

__device__ __forceinline__ void stcs2(float* p, float2 v) {
    asm volatile("st.global.cs.v2.f32 [%0], {%1, %2};" :: "l"(p), "f"(v.x), "f"(v.y));
}

__device__ __forceinline__ uint2 cvt4(float4 v) {
    __half2 h01 = __floats2half2_rn(v.x, v.y);
    __half2 h23 = __floats2half2_rn(v.z, v.w);
    return make_uint2(h2_as_u32(h01), h2_as_u32(h23));
}

// ============================================================================
// k_prep1: [0,64) histogram | [64,576) W->fp16
// ============================================================================
__global__ void __launch_bounds__(256) k_prep1(const float* __restrict__ W,
                                               const int* __restrict__ types) {
    const int bid = blockIdx.x, tid = threadIdx.x;

    if (bid < HIST_BLOCKS) {
        __shared__ int c[NTYPES];
        if (tid < NTYPES) c[tid] = 0;
        __syncthreads();
        int i = bid * 256 + tid;                       // [0, 16384)
        int4 tv = *(const int4*)(types + i * 4);
        atomicAdd(&c[tv.x], 1);
        atomicAdd(&c[tv.y], 1);
        atomicAdd(&c[tv.z], 1);
        atomicAdd(&c[tv.w], 1);
        __syncthreads();
        if (tid < NTYPES) atomicAdd(&g_counts[tid], c[tid]);
        return;
    }
    // ---- W convert: fp32 -> fp16 ----
    int i4 = (bid - HIST_BLOCKS) * 256 + tid;          // [0, 131072)
    float4 v = *(const float4*)(W + (size_t)i4 * 4);
    *(uint2*)(g_Wh + (size_t)i4 * 4) = cvt4(v);
}

// ============================================================================
// k_scan: prefix offsets, tile->type table, padded-slot marking
// ============================================================================
__global__ void k_scan() {
    __shared__ int s_start[NTYPES], s_tiles[NTYPES];
    int tid = threadIdx.x;
    if (tid == 0) {
        int off = 0;
        for (int t = 0; t < NTYPES; t++) {
            s_start[t] = off;
            g_padstart[t] = off;
            int tt = (g_counts[t] + BM - 1) / BM;
            s_tiles[t] = tt;
            off += tt * BM;
        }
    }
    __syncthreads();
    for (int tile = tid; tile < MAXTILES; tile += blockDim.x) {
        int ty = -1;
        int rb = tile * BM;
        for (int t = 0; t < NTYPES; t++)
            if (rb >= s_start[t] && rb < s_start[t] + s_tiles[t] * BM) ty = t;
        g_tiletype[tile] = ty;
    }
    for (int j = tid; j < NTYPES * BM; j += blockDim.x) {
        int t = j / BM, o = j % BM;
        int slot = g_counts[t] + o;
        if (slot < s_tiles[t] * BM) g_idx[s_start[t] + slot] = -1;
    }
}

// ============================================================================
// k_scatter: scatter rows by type + self-reset of counters for graph replay
// ============================================================================
__global__ void __launch_bounds__(256) k_scatter(const int* __restrict__ types) {
    __shared__ int c[NTYPES], base[NTYPES];
    int tid = threadIdx.x;
    if (tid < NTYPES) c[tid] = 0;
    __syncthreads();
    int i = blockIdx.x * 256 + tid;                    // [0, 16384)
    int4 tv = *(const int4*)(types + i * 4);
    int p0 = atomicAdd(&c[tv.x], 1);
    int p1 = atomicAdd(&c[tv.y], 1);
    int p2 = atomicAdd(&c[tv.z], 1);
    int p3 = atomicAdd(&c[tv.w], 1);
    __syncthreads();
    if (tid < NTYPES) base[tid] = atomicAdd(&g_cursor[tid], c[tid]);
    __syncthreads();
    g_idx[g_padstart[tv.x] + base[tv.x] + p0] = i * 4;
    g_idx[g_padstart[tv.y] + base[tv.y] + p1] = i * 4 + 1;
    g_idx[g_padstart[tv.z] + base[tv.z] + p2] = i * 4 + 2;
    g_idx[g_padstart[tv.w] + base[tv.w] + p3] = i * 4 + 3;
    if (tid < NTYPES) {
        atomicSub(&g_counts[tid], c[tid]);
        atomicSub(&g_cursor[tid], c[tid]);
    }
}

// ============================================================================
// Grouped GEMM: block = (row-tile, N-half). D[128,128] = gather(x)*Wh^T + b
// A: cp.async fp32 (pitch 272B) -> per-ks LDS.64 + cvt to fp16 fragments.
// B: cp.async fp16 SW128 -> ldmatrix. 8 warps in 4(M)x2(N); warp tile 32x64.
// 64 fp32 acc/thread; 2 CTAs/SM; 2-stage pipeline.
// ============================================================================
__global__ void __launch_bounds__(GTHREADS, 2)
typed_linear_gemm(const float* __restrict__ x, const float* __restrict__ b,
                  float* __restrict__ out) {
    extern __shared__ char smem[];
    const int tile  = blockIdx.x >> 1;
    const int nside = blockIdx.x & 1;
    const int t = g_tiletype[tile];
    if (t < 0) return;

    const int tid  = threadIdx.x;
    const int wid  = tid >> 5;
    const int lane = tid & 31;
    const uint32_t sb = smem_u32(smem);

    int*   s_idx  = (int*)smem;
    float* s_bias = (float*)(smem + 512);

    if (tid < BM) s_idx[tid] = g_idx[tile * BM + tid];
    if (tid < BN) s_bias[tid] = b[t * OUT_DIM + nside * BN + tid];
    __syncthreads();

    const __half* Wh_t = g_Wh + ((size_t)t * OUT_DIM + nside * BN) * IN_DIM;

    // Per chunk: A = 128 rows x 64 fp32 gathered (2048 x 16B, 8/thread, pitch 272),
    //            B = 128 rows x 64 fp16 SW128    (1024 x 16B, 4/thread).
    auto issue_chunk = [&](int c) {
        const int kb = c * KC;
        const uint32_t stg = sb + OFF_STAGE0 + (uint32_t)(c & 1) * STAGE_BYTES;
        #pragma unroll
        for (int r = 0; r < 8; ++r) {
            int i16 = r * GTHREADS + tid;          // [0,2048)
            int m = i16 >> 4, k4 = i16 & 15;
            int g = s_idx[m];
            cpa16(stg + (uint32_t)(m * A_PITCH + k4 * 16),
                  x + (size_t)(g < 0 ? 0 : g) * IN_DIM + kb + k4 * 4);
        }
        #pragma unroll
        for (int r = 0; r < 4; ++r) {
            int i16 = r * GTHREADS + tid;          // [0,1024)
            int n = i16 >> 3, k16 = i16 & 7;
            uint32_t d = swz((uint32_t)(n * 128 + k16 * 16));
            cpa16(stg + A_BYTES + d, Wh_t + (size_t)n * IN_DIM + kb + k16 * 8);
        }
        cpa_commit();
    };

    // -------- warp/lane constants --------
    const int mgrp = wid >> 1;      // rows [32*mgrp, +32)
    const int nq   = wid & 1;       // cols [64*nq, +64) within the 128-col tile
    const int j = lane & 7, sub = lane >> 3;

    // A fragment source rows/cols (fp32 smem, no ldmatrix):
    // lane needs A[r][k..k+1] at r = mgrp*32 + mt*16 + lane/4 (+8),
    //                            k = ks*16 + (lane%4)*2 (+8)
    const int a_r0   = mgrp * 32 + (lane >> 2);
    const int a_kby  = (lane & 3) * 8;             // byte offset of k within ks-block

    // B ldmatrix constants: 4 n16 tiles per warp
    uint32_t b_base[4], b_xr[4];
    #pragma unroll
    for (int nt = 0; nt < 4; ++nt) {
        int row = nq * 64 + nt * 16 + (sub >> 1) * 8 + j;
        b_xr[nt]   = (uint32_t)((row & 7) * 16);
        b_base[nt] = (uint32_t)(row * 128) + (uint32_t)((sub & 1) * 16);
    }

    float acc[2][8][4];   // [mt][n8][quad]
    #pragma unroll
    for (int mt = 0; mt < 2; ++mt)
        #pragma unroll
        for (int i = 0; i < 8; ++i)
            #pragma unroll
            for (int q = 0; q < 4; ++q) acc[mt][i][q] = 0.f;

    issue_chunk(0);

    #pragma unroll
    for (int c = 0; c < NCHUNK; ++c) {
        const uint32_t stg_off = OFF_STAGE0 + (uint32_t)(c & 1) * STAGE_BYTES;
        const uint32_t Bh = sb + stg_off + A_BYTES;
        const char* Af = smem + stg_off;           // fp32 A tile, pitch 272

        cpa_wait<0>();            // chunk c arrived
        __syncthreads();          // all warps done with the other stage

        if (c + 1 < NCHUNK) issue_chunk(c + 1);

        // ---- compute chunk c: 4 K16 steps ----
        #pragma unroll
        for (int ks = 0; ks < 4; ++ks) {
            const int kbyte = ks * 64 + a_kby;     // fp32 byte offset of lane's k
            // A fragments: LDS.64 + cvt, fragment regs {a0,a1,a2,a3}
            uint32_t ah[2][4];
            #pragma unroll
            for (int mt = 0; mt < 2; ++mt) {
                const char* rowp = Af + (a_r0 + mt * 16) * A_PITCH + kbyte;
                float2 v00 = *(const float2*)(rowp);
                float2 v10 = *(const float2*)(rowp + 8 * A_PITCH);
                float2 v01 = *(const float2*)(rowp + 32);
                float2 v11 = *(const float2*)(rowp + 8 * A_PITCH + 32);
                ah[mt][0] = h2_as_u32(__floats2half2_rn(v00.x, v00.y));
                ah[mt][1] = h2_as_u32(__floats2half2_rn(v10.x, v10.y));
                ah[mt][2] = h2_as_u32(__floats2half2_rn(v01.x, v01.y));
                ah[mt][3] = h2_as_u32(__floats2half2_rn(v11.x, v11.y));
            }
            const uint32_t kb16 = (uint32_t)(ks * 32);
            uint32_t bhr[4][4];
            #pragma unroll
            for (int nt = 0; nt < 4; ++nt)
                ldsm4(bhr[nt], Bh + ((b_base[nt] + kb16) ^ b_xr[nt]));
            #pragma unroll
            for (int nt = 0; nt < 4; ++nt)
                #pragma unroll
                for (int mt = 0; mt < 2; ++mt) {
                    mma16816(acc[mt][2 * nt],     ah[mt], bhr[nt][0], bhr[nt][1]);
                    mma16816(acc[mt][2 * nt + 1], ah[mt], bhr[nt][2], bhr[nt][3]);
                }
        }
    }

    // ---- epilogue: bias + scatter-store (streaming) ----
    #pragma unroll
    for (int mt = 0; mt < 2; ++mt) {
        const int r0 = mgrp * 32 + mt * 16 + (lane >> 2);
        const int g0 = s_idx[r0];
        const int g1 = s_idx[r0 + 8];
        #pragma unroll
        for (int n8 = 0; n8 < 8; ++n8) {
            const int lcol = nq * 64 + n8 * 8 + (lane & 3) * 2;
            const int col  = nside * BN + lcol;
            const float bv0 = s_bias[lcol], bv1 = s_bias[lcol + 1];
            if (g0 >= 0)
                stcs2(out + (size_t)g0 * OUT_DIM + col,
                      make_float2(acc[mt][n8][0] + bv0, acc[mt][n8][1] + bv1));
            if (g1 >= 0)
                stcs2(out + (size_t)g1 * OUT_DIM + col,
                      make_float2(acc[mt][n8][2] + bv0, acc[mt][n8][3] + bv1));
        }
    }
}

// ============================================================================
// Launch
// ============================================================================
extern "C" void kernel_launch(void* const* d_in, const int* in_sizes, int n_in,
                              void* d_out, int out_size) {
    const float* x     = (const float*)d_in[0];
    const int*   types = (const int*)d_in[1];
    const float* W     = (const float*)d_in[2];
    const float* b     = (const float*)d_in[3];
    float*       out   = (float*)d_out;

    cudaFuncSetAttribute(typed_linear_gemm, cudaFuncAttributeMaxDynamicSharedMemorySize,
                         SMEM_BYTES);

    k_prep1<<<HIST_BLOCKS + WCONV_BLOCKS, 256>>>(W, types);
    k_scan<<<1, 256>>>();
    k_scatter<<<HIST_BLOCKS, 256>>>(types);
    typed_linear_gemm<<<MAXTILES * 2, GTHREADS, SMEM_BYTES>>>(x, b, out);
}

// round 11
// speedup vs baseline: 1.0728x; 1.0728x over previous
#include <cuda_runtime.h>
#include <cuda_fp16.h>
#include <cstdint>

// ============================================================================
// Problem constants
// ============================================================================
#define N_ROWS   65536
#define IN_DIM   256
#define OUT_DIM  256
#define NTYPES   8
#define BM       64                        // rows per block tile
#define BN       256                       // cols per block tile (full OUT)
#define MAXTILES (N_ROWS / BM + NTYPES)    // 1032
#define KC       32                        // K-chunk (floats)
#define NCHUNK   (IN_DIM / KC)             // 8
#define GTHREADS 256
#define HIST_BLOCKS 64
#define WCONV_BLOCKS 512

// SMEM layout (bytes):
//  [0]      s_idx[64]      256B
//  [256]    s_bias[256]    1KB
//  [1536]   3 stages x (Araw fp32 64x128B = 8192 | B fp16 256x80B = 20480)
//  [87552]  Afp16 64x80B = 5120 (single buffer)
#define OFF_STAGE0  1536
#define A_RAW_BYTES 8192
#define B_PITCH     80
#define B_BYTES     (256 * B_PITCH)            // 20480
#define STAGE_BYTES (A_RAW_BYTES + B_BYTES)    // 28672
#define OFF_AF16    (OFF_STAGE0 + 3 * STAGE_BYTES)   // 87552
#define A_PITCH     80
#define SMEM_BYTES  (OFF_AF16 + 64 * A_PITCH)        // 92672

// ============================================================================
// Device scratch
// ============================================================================
__device__ int g_counts[NTYPES];   // self-resetting across graph replays
__device__ int g_cursor[NTYPES];   // self-resetting across graph replays
__device__ int g_padstart[NTYPES];
__device__ int g_idx[MAXTILES * BM];
__device__ int g_tiletype[MAXTILES];
__device__ __align__(16) __half g_Wh[NTYPES * OUT_DIM * IN_DIM];

// ============================================================================
// Helpers
// ============================================================================
__device__ __forceinline__ uint32_t smem_u32(const void* p) {
    uint32_t a;
    asm("{ .reg .u64 t; cvta.to.shared.u64 t, %1; cvt.u32.u64 %0, t; }" : "=r"(a) : "l"(p));
    return a;
}

__device__ __forceinline__ void cpa16(uint32_t dst, const void* src) {
    asm volatile("cp.async.cg.shared.global [%0], [%1], 16;" :: "r"(dst), "l"(src));
}
__device__ __forceinline__ void cpa_commit() {
    asm volatile("cp.async.commit_group;");
}
template <int N> __device__ __forceinline__ void cpa_wait() {
    asm volatile("cp.async.wait_group %0;" :: "n"(N) : "memory");
}

__device__ __forceinline__ void ldsm4(uint32_t* r, uint32_t addr) {
    asm volatile("ldmatrix.sync.aligned.m8n8.x4.shared.b16 {%0,%1,%2,%3}, [%4];"
                 : "=r"(r[0]), "=r"(r[1]), "=r"(r[2]), "=r"(r[3]) : "r"(addr));
}

__device__ __forceinline__ void mma16816(float* c, const uint32_t* a, uint32_t b0, uint32_t b1) {
    asm volatile("mma.sync.aligned.m16n8k16.row.col.f32.f16.f16.f32 "
                 "{%0,%1,%2,%3}, {%4,%5,%6,%7}, {%8,%9}, {%0,%1,%2,%3};"
                 : "+f"(c[0]), "+f"(c[1]), "+f"(c[2]), "+f"(c[3])
                 : "r"(a[0]), "r"(a[1]), "r"(a[2]), "r"(a[3]), "r"(b0), "r"(b1));
}

__device__ __forceinline__ uint32_t h2_as_u32(__half2 h) {
    return *reinterpret_cast<uint32_t*>(&h);
}

__device__ __forceinline__ void stcs2(float* p, float2 v) {
    asm volatile("st.global.cs.v2.f32 [%0], {%1, %2};" :: "l"(p), "f"(v.x), "f"(v.y));
}

__device__ __forceinline__ uint2 cvt4(float4 v) {
    __half2 h01 = __floats2half2_rn(v.x, v.y);
    __half2 h23 = __floats2half2_rn(v.z, v.w);
    return make_uint2(h2_as_u32(h01), h2_as_u32(h23));
}

// ============================================================================
// k_prep1: [0,64) histogram | [64,576) W->fp16
// ============================================================================
__global__ void __launch_bounds__(256) k_prep1(const float* __restrict__ W,
                                               const int* __restrict__ types) {
    const int bid = blockIdx.x, tid = threadIdx.x;

    if (bid < HIST_BLOCKS) {
        __shared__ int c[NTYPES];
        if (tid < NTYPES) c[tid] = 0;
        __syncthreads();
        int i = bid * 256 + tid;                       // [0, 16384)
        int4 tv = *(const int4*)(types + i * 4);
        atomicAdd(&c[tv.x], 1);
        atomicAdd(&c[tv.y], 1);
        atomicAdd(&c[tv.z], 1);
        atomicAdd(&c[tv.w], 1);
        __syncthreads();
        if (tid < NTYPES) atomicAdd(&g_counts[tid], c[tid]);
        return;
    }
    // ---- W convert: fp32 -> fp16 ----
    int i4 = (bid - HIST_BLOCKS) * 256 + tid;          // [0, 131072)
    float4 v = *(const float4*)(W + (size_t)i4 * 4);
    *(uint2*)(g_Wh + (size_t)i4 * 4) = cvt4(v);
}

// ============================================================================
// k_scan: prefix offsets, tile->type table, padded-slot marking
// ============================================================================
__global__ void k_scan() {
    __shared__ int s_start[NTYPES], s_tiles[NTYPES];
    int tid = threadIdx.x;
    if (tid == 0) {
        int off = 0;
        for (int t = 0; t < NTYPES; t++) {
            s_start[t] = off;
            g_padstart[t] = off;
            int tt = (g_counts[t] + BM - 1) / BM;
            s_tiles[t] = tt;
            off += tt * BM;
        }
    }
    __syncthreads();
    for (int tile = tid; tile < MAXTILES; tile += blockDim.x) {
        int ty = -1;
        int rb = tile * BM;
        for (int t = 0; t < NTYPES; t++)
            if (rb >= s_start[t] && rb < s_start[t] + s_tiles[t] * BM) ty = t;
        g_tiletype[tile] = ty;
    }
    for (int j = tid; j < NTYPES * BM; j += blockDim.x) {
        int t = j / BM, o = j % BM;
        int slot = g_counts[t] + o;
        if (slot < s_tiles[t] * BM) g_idx[s_start[t] + slot] = -1;
    }
}

// ============================================================================
// k_scatter: scatter rows by type + self-reset of counters for graph replay
// ============================================================================
__global__ void __launch_bounds__(256) k_scatter(const int* __restrict__ types) {
    __shared__ int c[NTYPES], base[NTYPES];
    int tid = threadIdx.x;
    if (tid < NTYPES) c[tid] = 0;
    __syncthreads();
    int i = blockIdx.x * 256 + tid;                    // [0, 16384)
    int4 tv = *(const int4*)(types + i * 4);
    int p0 = atomicAdd(&c[tv.x], 1);
    int p1 = atomicAdd(&c[tv.y], 1);
    int p2 = atomicAdd(&c[tv.z], 1);
    int p3 = atomicAdd(&c[tv.w], 1);
    __syncthreads();
    if (tid < NTYPES) base[tid] = atomicAdd(&g_cursor[tid], c[tid]);
    __syncthreads();
    g_idx[g_padstart[tv.x] + base[tv.x] + p0] = i * 4;
    g_idx[g_padstart[tv.y] + base[tv.y] + p1] = i * 4 + 1;
    g_idx[g_padstart[tv.z] + base[tv.z] + p2] = i * 4 + 2;
    g_idx[g_padstart[tv.w] + base[tv.w] + p3] = i * 4 + 3;
    if (tid < NTYPES) {
        atomicSub(&g_counts[tid], c[tid]);
        atomicSub(&g_cursor[tid], c[tid]);
    }
}

// ============================================================================
// Grouped GEMM: one CTA per row-tile. D[64,256] = gather(x) * Wh[t]^T + b[t]
// A: cp.async raw fp32 -> bulk convert phase -> fp16 (pitch 80B) -> ldmatrix.
// B: cp.async fp16 (pitch 80B) -> ldmatrix.  Rows 0-7 at pitch 80 hit bank
// offsets {0,20,8,28,16,4,24,12}: conflict-free without swizzle.
// 8 warps in 2(M)x4(N); warp tile 32x64; 64 fp32 acc/thread; 2 CTAs/SM.
// 3-stage pipeline, prefetch depth 2, KC=32 (8 chunks).
// ============================================================================
__global__ void __launch_bounds__(GTHREADS, 2)
typed_linear_gemm(const float* __restrict__ x, const float* __restrict__ b,
                  float* __restrict__ out) {
    extern __shared__ char smem[];
    const int tile = blockIdx.x;
    const int t = g_tiletype[tile];
    if (t < 0) return;

    const int tid  = threadIdx.x;
    const int wid  = tid >> 5;
    const int lane = tid & 31;
    const uint32_t sb = smem_u32(smem);

    int*   s_idx  = (int*)smem;
    float* s_bias = (float*)(smem + 256);

    if (tid < BM) s_idx[tid] = g_idx[tile * BM + tid];
    s_bias[tid] = b[t * OUT_DIM + tid];
    __syncthreads();

    const __half* Wh_t = g_Wh + (size_t)t * OUT_DIM * IN_DIM;

    // Per chunk: Araw = 64 rows x 32 fp32 (512 x 16B, 2/thread, pitch 128B),
    //            B    = 256 rows x 32 fp16 (1024 x 16B, 4/thread, pitch 80B).
    auto issue_chunk = [&](int c) {
        const int kb = c * KC;
        const uint32_t stg = sb + OFF_STAGE0 + (uint32_t)(c % 3) * STAGE_BYTES;
        #pragma unroll
        for (int r = 0; r < 2; ++r) {
            int i16 = r * GTHREADS + tid;          // [0,512)
            int m = i16 >> 3, k4 = i16 & 7;
            int g = s_idx[m];
            cpa16(stg + (uint32_t)(m * 128 + k4 * 16),
                  x + (size_t)(g < 0 ? 0 : g) * IN_DIM + kb + k4 * 4);
        }
        #pragma unroll
        for (int r = 0; r < 4; ++r) {
            int i16 = r * GTHREADS + tid;          // [0,1024)
            int n = i16 >> 2, k16 = i16 & 3;
            cpa16(stg + A_RAW_BYTES + (uint32_t)(n * B_PITCH + k16 * 16),
                  Wh_t + (size_t)n * IN_DIM + kb + k16 * 8);
        }
        cpa_commit();
    };

    // -------- warp/lane constants --------
    const int mgrp = wid >> 2;      // rows [32*mgrp, +32)
    const int nq   = wid & 3;       // cols [64*nq, +64)
    const int j = lane & 7, sub = lane >> 3;

    const uint32_t Af = sb + OFF_AF16;
    uint32_t a_base[2];
    #pragma unroll
    for (int mt = 0; mt < 2; ++mt) {
        int row = mgrp * 32 + mt * 16 + j + (sub & 1) * 8;
        a_base[mt] = (uint32_t)(row * A_PITCH) + (uint32_t)((sub >> 1) * 16);
    }
    uint32_t b_base[4];
    #pragma unroll
    for (int nt = 0; nt < 4; ++nt) {
        int row = nq * 64 + nt * 16 + (sub >> 1) * 8 + j;
        b_base[nt] = (uint32_t)(row * B_PITCH) + (uint32_t)((sub & 1) * 16);
    }

    float acc[2][8][4];   // [mt][n8][quad]
    #pragma unroll
    for (int mt = 0; mt < 2; ++mt)
        #pragma unroll
        for (int i = 0; i < 8; ++i)
            #pragma unroll
            for (int q = 0; q < 4; ++q) acc[mt][i][q] = 0.f;

    issue_chunk(0);
    issue_chunk(1);

    #pragma unroll
    for (int c = 0; c < NCHUNK; ++c) {
        const uint32_t stg_off = OFF_STAGE0 + (uint32_t)(c % 3) * STAGE_BYTES;
        const uint32_t Bh = sb + stg_off + A_RAW_BYTES;

        if (c == NCHUNK - 1) cpa_wait<0>(); else cpa_wait<1>();   // chunk c arrived
        __syncthreads();   // all warps past compute(c-1) (Afp16 + old stages free)

        // ---- bulk convert Araw(c) fp32 -> Afp16 (pitch 80) ----
        #pragma unroll
        for (int r = 0; r < 2; ++r) {
            int i4 = r * GTHREADS + tid;           // [0,512)
            int m = i4 >> 3, k4 = i4 & 7;
            float4 v = *(const float4*)(smem + stg_off + m * 128 + k4 * 16);
            if (s_idx[m] < 0) v = make_float4(0.f, 0.f, 0.f, 0.f);
            *(uint2*)(smem + (OFF_AF16) + m * A_PITCH + k4 * 8) = cvt4(v);
        }
        __syncthreads();   // Afp16 visible; Araw(c) consumed

        if (c + 2 < NCHUNK) issue_chunk(c + 2);   // stage (c+2)%3: B(c-1)/Araw(c-1), both done

        // ---- compute chunk c: 2 K16 steps ----
        #pragma unroll
        for (int ks = 0; ks < 2; ++ks) {
            const uint32_t kbyte = (uint32_t)(ks * 32);
            uint32_t ah[2][4], bhr[4][4];
            #pragma unroll
            for (int mt = 0; mt < 2; ++mt)
                ldsm4(ah[mt], Af + a_base[mt] + kbyte);
            #pragma unroll
            for (int nt = 0; nt < 4; ++nt)
                ldsm4(bhr[nt], Bh + b_base[nt] + kbyte);
            #pragma unroll
            for (int nt = 0; nt < 4; ++nt)
                #pragma unroll
                for (int mt = 0; mt < 2; ++mt) {
                    mma16816(acc[mt][2 * nt],     ah[mt], bhr[nt][0], bhr[nt][1]);
                    mma16816(acc[mt][2 * nt + 1], ah[mt], bhr[nt][2], bhr[nt][3]);
                }
        }
    }

    // ---- epilogue: bias + scatter-store (streaming) ----
    #pragma unroll
    for (int mt = 0; mt < 2; ++mt) {
        const int r0 = mgrp * 32 + mt * 16 + (lane >> 2);
        const int g0 = s_idx[r0];
        const int g1 = s_idx[r0 + 8];
        #pragma unroll
        for (int n8 = 0; n8 < 8; ++n8) {
            const int col = nq * 64 + n8 * 8 + (lane & 3) * 2;
            const float bv0 = s_bias[col], bv1 = s_bias[col + 1];
            if (g0 >= 0)
                stcs2(out + (size_t)g0 * OUT_DIM + col,
                      make_float2(acc[mt][n8][0] + bv0, acc[mt][n8][1] + bv1));
            if (g1 >= 0)
                stcs2(out + (size_t)g1 * OUT_DIM + col,
                      make_float2(acc[mt][n8][2] + bv0, acc[mt][n8][3] + bv1));
        }
    }
}

// ============================================================================
// Launch
// ============================================================================
extern "C" void kernel_launch(void* const* d_in, const int* in_sizes, int n_in,
                              void* d_out, int out_size) {
    const float* x     = (const float*)d_in[0];
    const int*   types = (const int*)d_in[1];
    const float* W     = (const float*)d_in[2];
    const float* b     = (const float*)d_in[3];
    float*       out   = (float*)d_out;

    cudaFuncSetAttribute(typed_linear_gemm, cudaFuncAttributeMaxDynamicSharedMemorySize,
                         SMEM_BYTES);

    k_prep1<<<HIST_BLOCKS + WCONV_BLOCKS, 256>>>(W, types);
    k_scan<<<1, 256>>>();
    k_scatter<<<HIST_BLOCKS, 256>>>(types);
    typed_linear_gemm<<<MAXTILES, GTHREADS, SMEM_BYTES>>>(x, b, out);
}